// round 2
// baseline (speedup 1.0000x reference)
#include <cuda_runtime.h>

#define KDIM 64
#define CDIM 128
#define MAXSPLIT 320

// Scratch: split-N partials + reduced U/V + P/R
__device__ float g_part[2][MAXSPLIT][KDIM][CDIM];   // ~21 MB
__device__ float g_UV[2][KDIM][CDIM];
__device__ float g_PR[2][KDIM][CDIM];

// ---------------------------------------------------------------------------
// Kernel 1: partial U/V over a 32-row slice of N.
//   U[k,c] = sum_n Qr[n,k]*re[n,c] + Qi[n,k]*im[n,c]
//   V[k,c] = sum_n Qi[n,k]*re[n,c] - Qr[n,k]*im[n,c]
// grid = nsplit (~313), block (16,16); thread = 4k x 8c micro-tile, full C.
// ---------------------------------------------------------------------------
__global__ __launch_bounds__(256, 2) void k1_partial(
    const float* __restrict__ Qr, const float* __restrict__ Qi,
    const float* __restrict__ re, const float* __restrict__ im, int N)
{
    __shared__ float sQr[32][64];
    __shared__ float sQi[32][64];
    __shared__ float sRe[32][128];
    __shared__ float sIm[32][128];

    const int s  = blockIdx.x;
    const int n0 = s * 32;
    const int tx = threadIdx.x, ty = threadIdx.y;
    const int tid = ty * 16 + tx;
    const float4 z4 = make_float4(0.f, 0.f, 0.f, 0.f);

    // Load Q tiles: 32 rows x 16 float4 = 512 float4 per array (2 passes)
    #pragma unroll
    for (int q = 0; q < 2; q++) {
        int f = tid + 256 * q;
        int row = f >> 4;
        int c4  = (f & 15) * 4;
        int n   = n0 + row;
        float4 a = z4, b = z4;
        if (n < N) {
            a = *(const float4*)(Qr + (long)n * 64 + c4);
            b = *(const float4*)(Qi + (long)n * 64 + c4);
        }
        *(float4*)&sQr[row][c4] = a;
        *(float4*)&sQi[row][c4] = b;
    }
    // Load X tiles: 32 rows x 32 float4 = 1024 float4 per array (4 passes)
    #pragma unroll
    for (int q = 0; q < 4; q++) {
        int f = tid + 256 * q;
        int row = f >> 5;
        int c4  = (f & 31) * 4;
        int n   = n0 + row;
        float4 x = z4, y = z4;
        if (n < N) {
            x = *(const float4*)(re + (long)n * 128 + c4);
            y = *(const float4*)(im + (long)n * 128 + c4);
        }
        *(float4*)&sRe[row][c4] = x;
        *(float4*)&sIm[row][c4] = y;
    }
    __syncthreads();

    float u[4][8] = {};
    float v[4][8] = {};

    #pragma unroll 8
    for (int r = 0; r < 32; r++) {
        float4 q4 = *(float4*)&sQr[r][ty * 4];
        float4 g4 = *(float4*)&sQi[r][ty * 4];
        float4 xa = *(float4*)&sRe[r][tx * 8];
        float4 xb = *(float4*)&sRe[r][tx * 8 + 4];
        float4 ya = *(float4*)&sIm[r][tx * 8];
        float4 yb = *(float4*)&sIm[r][tx * 8 + 4];
        float qr[4] = {q4.x, q4.y, q4.z, q4.w};
        float qi[4] = {g4.x, g4.y, g4.z, g4.w};
        float xr[8] = {xa.x, xa.y, xa.z, xa.w, xb.x, xb.y, xb.z, xb.w};
        float xi[8] = {ya.x, ya.y, ya.z, ya.w, yb.x, yb.y, yb.z, yb.w};
        #pragma unroll
        for (int i = 0; i < 4; i++)
            #pragma unroll
            for (int j = 0; j < 8; j++) {
                u[i][j] += qr[i] * xr[j] + qi[i] * xi[j];
                v[i][j] += qi[i] * xr[j] - qr[i] * xi[j];
            }
    }

    #pragma unroll
    for (int i = 0; i < 4; i++) {
        int k = ty * 4 + i;
        *(float4*)&g_part[0][s][k][tx * 8]     = make_float4(u[i][0], u[i][1], u[i][2], u[i][3]);
        *(float4*)&g_part[0][s][k][tx * 8 + 4] = make_float4(u[i][4], u[i][5], u[i][6], u[i][7]);
        *(float4*)&g_part[1][s][k][tx * 8]     = make_float4(v[i][0], v[i][1], v[i][2], v[i][3]);
        *(float4*)&g_part[1][s][k][tx * 8 + 4] = make_float4(v[i][4], v[i][5], v[i][6], v[i][7]);
    }
}

// ---------------------------------------------------------------------------
// Kernel 2a: reduce partials over splits (8-way parallel per output),
// scale row k by TT = Ritz[k]^long_diff.
// grid 512, block 256 = 32 outputs x 8 split-segments.
// ---------------------------------------------------------------------------
__global__ __launch_bounds__(256) void k2a_reduce(
    const float* __restrict__ Ritz, const int* __restrict__ ldp, int nsplit)
{
    __shared__ float red[256];
    const int o   = threadIdx.x & 31;
    const int seg = threadIdx.x >> 5;
    const int t   = blockIdx.x * 32 + o;       // 0..16383
    const int uv  = t >> 13;
    const int rem = t & 8191;

    const float* p = &g_part[uv][0][0][0] + rem;
    float sum = 0.f;
    for (int s = seg; s < nsplit; s += 8) sum += p[(long)s * 8192];
    red[threadIdx.x] = sum;
    __syncthreads();

    if (threadIdx.x < 32) {
        #pragma unroll
        for (int g = 1; g < 8; g++) sum += red[g * 32 + o];
        int k = rem >> 7;
        int ld = *ldp;
        float rz = Ritz[k];
        float tt = 1.f;
        for (int i = 0; i < ld; i++) tt *= rz;
        (&g_UV[0][0][0])[t] = tt * sum;
    }
}

// ---------------------------------------------------------------------------
// Kernel 2b: P = U' @ W, R = V' @ W   ([64,128] @ [128,128])
// grid (2 matrices, 2 c'-halves), block (16,16), 4x4 micro-tile.
// ---------------------------------------------------------------------------
__global__ __launch_bounds__(256) void k2b_pr(const float* __restrict__ W)
{
    __shared__ float sA[64 * 68];   // [k][cc-chunk], pitch 68
    __shared__ float sW[64 * 64];   // [cc-chunk][c']

    const int m   = blockIdx.x;
    const int cp0 = blockIdx.y * 64;
    const int tx = threadIdx.x, ty = threadIdx.y;
    const int tid = ty * 16 + tx;

    float acc[4][4] = {};

    for (int cc = 0; cc < 128; cc += 64) {
        #pragma unroll
        for (int q = 0; q < 4; q++) {
            int f   = tid + 256 * q;
            int row = f >> 4;
            int c4  = (f & 15) * 4;
            *(float4*)&sA[row * 68 + c4] = *(const float4*)&g_UV[m][row][cc + c4];
            *(float4*)&sW[row * 64 + c4] = *(const float4*)(W + (cc + row) * 128 + cp0 + c4);
        }
        __syncthreads();

        #pragma unroll 4
        for (int r = 0; r < 64; r++) {
            float a[4];
            #pragma unroll
            for (int i = 0; i < 4; i++) a[i] = sA[(ty * 4 + i) * 68 + r];
            float4 w4 = *(float4*)&sW[r * 64 + tx * 4];
            float wj[4] = {w4.x, w4.y, w4.z, w4.w};
            #pragma unroll
            for (int i = 0; i < 4; i++)
                #pragma unroll
                for (int j = 0; j < 4; j++)
                    acc[i][j] += a[i] * wj[j];
        }
        __syncthreads();
    }

    #pragma unroll
    for (int i = 0; i < 4; i++)
        *(float4*)&g_PR[m][ty * 4 + i][cp0 + tx * 4] =
            make_float4(acc[i][0], acc[i][1], acc[i][2], acc[i][3]);
}

// ---------------------------------------------------------------------------
// Kernel 3: res_real = Qr@P + Qi@R, res_imag = Qi@P - Qr@R, masked-ReLU add.
// grid = ceil(N/32), block (16,16); thread = 2 rows x 8 cols, full C tile.
// ---------------------------------------------------------------------------
__global__ __launch_bounds__(256, 2) void k3_out(
    const float* __restrict__ Qr, const float* __restrict__ Qi,
    const float* __restrict__ re, const float* __restrict__ im,
    float* __restrict__ out, int N)
{
    __shared__ float sQr[32][32];   // [n-local][k-chunk]
    __shared__ float sQi[32][32];
    __shared__ float sP [32][128];  // [k-chunk][c]
    __shared__ float sR [32][128];

    const int n0 = blockIdx.x * 32;
    const int tx = threadIdx.x, ty = threadIdx.y;
    const int tid = ty * 16 + tx;
    const float4 z4 = make_float4(0.f, 0.f, 0.f, 0.f);

    float sr[2][8] = {};
    float si[2][8] = {};

    for (int kk = 0; kk < 64; kk += 32) {
        // Q tiles: 32 rows x 8 float4 = 256 float4 each (1 pass each)
        {
            int row = tid >> 3;
            int c4  = (tid & 7) * 4;
            int n   = n0 + row;
            float4 a = z4, b = z4;
            if (n < N) {
                a = *(const float4*)(Qr + (long)n * 64 + kk + c4);
                b = *(const float4*)(Qi + (long)n * 64 + kk + c4);
            }
            *(float4*)&sQr[row][c4] = a;
            *(float4*)&sQi[row][c4] = b;
        }
        // P/R tiles: 32 k x 32 float4 = 1024 float4 each (4 passes each)
        #pragma unroll
        for (int q = 0; q < 4; q++) {
            int f   = tid + 256 * q;
            int row = f >> 5;
            int c4  = (f & 31) * 4;
            *(float4*)&sP[row][c4] = *(const float4*)&g_PR[0][kk + row][c4];
            *(float4*)&sR[row][c4] = *(const float4*)&g_PR[1][kk + row][c4];
        }
        __syncthreads();

        #pragma unroll 16
        for (int r = 0; r < 32; r++) {
            float qr0 = sQr[ty * 2 + 0][r];
            float qr1 = sQr[ty * 2 + 1][r];
            float qi0 = sQi[ty * 2 + 0][r];
            float qi1 = sQi[ty * 2 + 1][r];
            float4 pa = *(float4*)&sP[r][tx * 8];
            float4 pb = *(float4*)&sP[r][tx * 8 + 4];
            float4 ra = *(float4*)&sR[r][tx * 8];
            float4 rb = *(float4*)&sR[r][tx * 8 + 4];
            float pj[8] = {pa.x, pa.y, pa.z, pa.w, pb.x, pb.y, pb.z, pb.w};
            float rj[8] = {ra.x, ra.y, ra.z, ra.w, rb.x, rb.y, rb.z, rb.w};
            #pragma unroll
            for (int j = 0; j < 8; j++) {
                sr[0][j] += qr0 * pj[j] + qi0 * rj[j];
                si[0][j] += qi0 * pj[j] - qr0 * rj[j];
                sr[1][j] += qr1 * pj[j] + qi1 * rj[j];
                si[1][j] += qi1 * pj[j] - qr1 * rj[j];
            }
        }
        __syncthreads();
    }

    const long NC = (long)N * 128;
    #pragma unroll
    for (int i = 0; i < 2; i++) {
        int n = n0 + ty * 2 + i;
        if (n >= N) continue;
        long base = (long)n * 128 + tx * 8;
        float4 rea = *(const float4*)(re + base);
        float4 reb = *(const float4*)(re + base + 4);
        float4 ima = *(const float4*)(im + base);
        float4 imb = *(const float4*)(im + base + 4);
        float rl[8] = {rea.x, rea.y, rea.z, rea.w, reb.x, reb.y, reb.z, reb.w};
        float il[8] = {ima.x, ima.y, ima.z, ima.w, imb.x, imb.y, imb.z, imb.w};
        float orr[8], oii[8];
        #pragma unroll
        for (int j = 0; j < 8; j++) {
            float mask = (sr[i][j] >= 0.f) ? 1.f : 0.f;
            orr[j] = rl[j] + mask * sr[i][j];
            oii[j] = il[j] + mask * si[i][j];
        }
        *(float4*)(out + base)          = make_float4(orr[0], orr[1], orr[2], orr[3]);
        *(float4*)(out + base + 4)      = make_float4(orr[4], orr[5], orr[6], orr[7]);
        *(float4*)(out + NC + base)     = make_float4(oii[0], oii[1], oii[2], oii[3]);
        *(float4*)(out + NC + base + 4) = make_float4(oii[4], oii[5], oii[6], oii[7]);
    }
}

// ---------------------------------------------------------------------------
extern "C" void kernel_launch(void* const* d_in, const int* in_sizes, int n_in,
                              void* d_out, int out_size)
{
    const float* real  = (const float*)d_in[0];
    const float* imag  = (const float*)d_in[1];
    const float* Qreal = (const float*)d_in[2];
    const float* Qimag = (const float*)d_in[3];
    const float* Ritz  = (const float*)d_in[4];
    const float* W     = (const float*)d_in[5];
    const int*   ldp   = (const int*)d_in[6];
    float* out = (float*)d_out;

    int N = in_sizes[0] / CDIM;
    int nsplit = (N + 31) / 32;   // 313 for N=10000, fits MAXSPLIT=320

    dim3 blk(16, 16);
    k1_partial<<<nsplit, blk>>>(Qreal, Qimag, real, imag, N);
    k2a_reduce<<<512, 256>>>(Ritz, ldp, nsplit);
    k2b_pr<<<dim3(2, 2), blk>>>(W);
    k3_out<<<nsplit, blk>>>(Qreal, Qimag, real, imag, out, N);
}

// round 3
// speedup vs baseline: 1.6241x; 1.6241x over previous
#include <cuda_runtime.h>

#define KDIM 64
#define CDIM 128
#define MAXSPLIT 160

__device__ float g_part[2][MAXSPLIT][KDIM][CDIM];   // ~10.3 MB used
__device__ float g_UV[2][KDIM][CDIM];
__device__ float g_PR[2][KDIM][CDIM];

typedef unsigned long long u64;

__device__ __forceinline__ void fma2(u64& d, u64 a, u64 b) {
    asm("fma.rn.f32x2 %0, %1, %2, %0;" : "+l"(d) : "l"(a), "l"(b));
}
__device__ __forceinline__ u64 neg2(u64 v) { return v ^ 0x8000000080000000ULL; }
__device__ __forceinline__ float2 unpk(u64 v) {
    float2 f; asm("mov.b64 {%0, %1}, %2;" : "=f"(f.x), "=f"(f.y) : "l"(v)); return f;
}

// ---------------------------------------------------------------------------
// Kernel 1: partial U/V over a 64-row slice of N (two 32-row chunks).
//   U[k,c] = sum_n Qr[n,k]*re[n,c] + Qi[n,k]*im[n,c]
//   V[k,c] = sum_n Qi[n,k]*re[n,c] - Qr[n,k]*im[n,c]
// grid (157, 2 c-halves), block (16,16); thread = 4k(x2 packs) x 4c.
// Accumulators packed over k (Q pairs native via LDS.128); re/im duplicated
// (x,x) in smem so the c-side operand is a direct LDS.64. Zero packing movs.
// ---------------------------------------------------------------------------
__global__ __launch_bounds__(256, 2) void k1_partial(
    const float* __restrict__ Qr, const float* __restrict__ Qi,
    const float* __restrict__ re, const float* __restrict__ im, int N)
{
    __shared__ float  sQr[32][64];
    __shared__ float  sQi[32][64];
    __shared__ float2 sReD[32][64];   // duplicated (x,x)
    __shared__ float2 sImD[32][64];

    const int s  = blockIdx.x;
    const int c0 = blockIdx.y * 64;
    const int tx = threadIdx.x, ty = threadIdx.y;
    const int tid = ty * 16 + tx;
    const float4 z4 = make_float4(0.f, 0.f, 0.f, 0.f);

    u64 u[2][4] = {};   // [k-pack][c]
    u64 v[2][4] = {};

    for (int rt = 0; rt < 64; rt += 32) {
        const int nb = s * 64 + rt;
        // Q tiles: 32 rows x 64 k = 512 float4 per array
        #pragma unroll
        for (int q = 0; q < 2; q++) {
            int f   = tid + 256 * q;
            int row = f >> 4;
            int k4  = (f & 15) * 4;
            int n   = nb + row;
            float4 a = z4, b = z4;
            if (n < N) {
                a = *(const float4*)(Qr + (long)n * 64 + k4);
                b = *(const float4*)(Qi + (long)n * 64 + k4);
            }
            *(float4*)&sQr[row][k4] = a;
            *(float4*)&sQi[row][k4] = b;
        }
        // X tiles (duplicated): 32 rows x 64 c-half = 512 float4 per array
        #pragma unroll
        for (int q = 0; q < 2; q++) {
            int f   = tid + 256 * q;
            int row = f >> 4;
            int c4  = (f & 15) * 4;
            int n   = nb + row;
            float4 x = z4, y = z4;
            if (n < N) {
                x = *(const float4*)(re + (long)n * 128 + c0 + c4);
                y = *(const float4*)(im + (long)n * 128 + c0 + c4);
            }
            sReD[row][c4 + 0] = make_float2(x.x, x.x);
            sReD[row][c4 + 1] = make_float2(x.y, x.y);
            sReD[row][c4 + 2] = make_float2(x.z, x.z);
            sReD[row][c4 + 3] = make_float2(x.w, x.w);
            sImD[row][c4 + 0] = make_float2(y.x, y.x);
            sImD[row][c4 + 1] = make_float2(y.y, y.y);
            sImD[row][c4 + 2] = make_float2(y.z, y.z);
            sImD[row][c4 + 3] = make_float2(y.w, y.w);
        }
        __syncthreads();

        #pragma unroll 4
        for (int r = 0; r < 32; r++) {
            ulonglong2 qr2 = *(const ulonglong2*)&sQr[r][ty * 4];
            ulonglong2 qi2 = *(const ulonglong2*)&sQi[r][ty * 4];
            u64 qr[2] = {qr2.x, qr2.y};
            u64 qi[2] = {qi2.x, qi2.y};
            u64 nq[2] = {neg2(qr2.x), neg2(qr2.y)};
            u64 xr[4], xi[4];
            #pragma unroll
            for (int j = 0; j < 4; j++) {
                xr[j] = *(const u64*)&sReD[r][tx * 4 + j];
                xi[j] = *(const u64*)&sImD[r][tx * 4 + j];
            }
            #pragma unroll
            for (int ip = 0; ip < 2; ip++)
                #pragma unroll
                for (int j = 0; j < 4; j++) {
                    fma2(u[ip][j], qr[ip], xr[j]);
                    fma2(u[ip][j], qi[ip], xi[j]);
                    fma2(v[ip][j], qi[ip], xr[j]);
                    fma2(v[ip][j], nq[ip], xi[j]);
                }
        }
        __syncthreads();
    }

    #pragma unroll
    for (int ip = 0; ip < 2; ip++) {
        float2 a0 = unpk(u[ip][0]), a1 = unpk(u[ip][1]), a2 = unpk(u[ip][2]), a3 = unpk(u[ip][3]);
        float2 b0 = unpk(v[ip][0]), b1 = unpk(v[ip][1]), b2 = unpk(v[ip][2]), b3 = unpk(v[ip][3]);
        int k = ty * 4 + ip * 2;
        int c = c0 + tx * 4;
        *(float4*)&g_part[0][s][k][c]     = make_float4(a0.x, a1.x, a2.x, a3.x);
        *(float4*)&g_part[0][s][k + 1][c] = make_float4(a0.y, a1.y, a2.y, a3.y);
        *(float4*)&g_part[1][s][k][c]     = make_float4(b0.x, b1.x, b2.x, b3.x);
        *(float4*)&g_part[1][s][k + 1][c] = make_float4(b0.y, b1.y, b2.y, b3.y);
    }
}

// ---------------------------------------------------------------------------
// Kernel 2a: reduce partials over splits (8-way parallel per output),
// scale row k by TT = Ritz[k]^long_diff.  grid 512, block 256.
// ---------------------------------------------------------------------------
__global__ __launch_bounds__(256) void k2a_reduce(
    const float* __restrict__ Ritz, const int* __restrict__ ldp, int nsplit)
{
    __shared__ float red[256];
    const int o   = threadIdx.x & 31;
    const int seg = threadIdx.x >> 5;
    const int t   = blockIdx.x * 32 + o;       // 0..16383
    const int uv  = t >> 13;
    const int rem = t & 8191;

    const float* p = &g_part[uv][0][0][0] + rem;
    float sum = 0.f;
    for (int s2 = seg; s2 < nsplit; s2 += 8) sum += p[(long)s2 * 8192];
    red[threadIdx.x] = sum;
    __syncthreads();

    if (threadIdx.x < 32) {
        #pragma unroll
        for (int g = 1; g < 8; g++) sum += red[g * 32 + o];
        int k = rem >> 7;
        int ld = *ldp;
        float rz = Ritz[k];
        float tt = 1.f;
        for (int i = 0; i < ld; i++) tt *= rz;
        (&g_UV[0][0][0])[t] = tt * sum;
    }
}

// ---------------------------------------------------------------------------
// Kernel 2b: P = U' @ W, R = V' @ W   ([64,128] @ [128,128])
// ---------------------------------------------------------------------------
__global__ __launch_bounds__(256) void k2b_pr(const float* __restrict__ W)
{
    __shared__ float sA[64 * 68];
    __shared__ float sW[64 * 64];

    const int m   = blockIdx.x;
    const int cp0 = blockIdx.y * 64;
    const int tx = threadIdx.x, ty = threadIdx.y;
    const int tid = ty * 16 + tx;

    float acc[4][4] = {};

    for (int cc = 0; cc < 128; cc += 64) {
        #pragma unroll
        for (int q = 0; q < 4; q++) {
            int f   = tid + 256 * q;
            int row = f >> 4;
            int c4  = (f & 15) * 4;
            *(float4*)&sA[row * 68 + c4] = *(const float4*)&g_UV[m][row][cc + c4];
            *(float4*)&sW[row * 64 + c4] = *(const float4*)(W + (cc + row) * 128 + cp0 + c4);
        }
        __syncthreads();

        #pragma unroll 4
        for (int r = 0; r < 64; r++) {
            float a[4];
            #pragma unroll
            for (int i = 0; i < 4; i++) a[i] = sA[(ty * 4 + i) * 68 + r];
            float4 w4 = *(float4*)&sW[r * 64 + tx * 4];
            float wj[4] = {w4.x, w4.y, w4.z, w4.w};
            #pragma unroll
            for (int i = 0; i < 4; i++)
                #pragma unroll
                for (int j = 0; j < 4; j++)
                    acc[i][j] += a[i] * wj[j];
        }
        __syncthreads();
    }

    #pragma unroll
    for (int i = 0; i < 4; i++)
        *(float4*)&g_PR[m][ty * 4 + i][cp0 + tx * 4] =
            make_float4(acc[i][0], acc[i][1], acc[i][2], acc[i][3]);
}

// ---------------------------------------------------------------------------
// Kernel 3: res_real = Qr@P + Qi@R, res_imag = Qi@P - Qr@R, masked-ReLU add.
// grid 313 (32 rows/CTA), block (16,8); thread = 4 rows x 8 cols (4 c-packs).
// Accumulators packed over c (P/R pairs native); Q stored in smem duplicated
// (q,q) plus a pre-negated copy, so inner loop has zero packing/negation.
// ---------------------------------------------------------------------------
__global__ __launch_bounds__(128) void k3_out(
    const float* __restrict__ Qr, const float* __restrict__ Qi,
    const float* __restrict__ re, const float* __restrict__ im,
    float* __restrict__ out, int N)
{
    __shared__ float2 sQrD[16][32];   // [k-chunk][n-local], dup (q,q)
    __shared__ float2 sQiD[16][32];
    __shared__ float2 sNQD[16][32];   // (-qr,-qr)
    __shared__ float  sP[16][128];
    __shared__ float  sR[16][128];

    const int n0 = blockIdx.x * 32;
    const int tx = threadIdx.x, ty = threadIdx.y;
    const int tid = ty * 16 + tx;     // 0..127
    const float4 z4 = make_float4(0.f, 0.f, 0.f, 0.f);

    u64 sr[4][4] = {};   // [row][c-pack]
    u64 si[4][4] = {};

    for (int kk = 0; kk < 64; kk += 16) {
        // Q tiles: 32 rows x 16 k = 128 float4 per array; 1 per thread
        {
            int row = tid >> 2;           // 4 float4 per 16-k row
            int k4  = (tid & 3) * 4;
            int n   = n0 + row;
            float4 a = z4, b = z4;
            if (n < N) {
                a = *(const float4*)(Qr + (long)n * 64 + kk + k4);
                b = *(const float4*)(Qi + (long)n * 64 + kk + k4);
            }
            sQrD[k4 + 0][row] = make_float2(a.x, a.x);
            sQrD[k4 + 1][row] = make_float2(a.y, a.y);
            sQrD[k4 + 2][row] = make_float2(a.z, a.z);
            sQrD[k4 + 3][row] = make_float2(a.w, a.w);
            sNQD[k4 + 0][row] = make_float2(-a.x, -a.x);
            sNQD[k4 + 1][row] = make_float2(-a.y, -a.y);
            sNQD[k4 + 2][row] = make_float2(-a.z, -a.z);
            sNQD[k4 + 3][row] = make_float2(-a.w, -a.w);
            sQiD[k4 + 0][row] = make_float2(b.x, b.x);
            sQiD[k4 + 1][row] = make_float2(b.y, b.y);
            sQiD[k4 + 2][row] = make_float2(b.z, b.z);
            sQiD[k4 + 3][row] = make_float2(b.w, b.w);
        }
        // P/R tiles: 16 k x 128 c = 512 float4 per array; 4 per thread each
        #pragma unroll
        for (int q = 0; q < 4; q++) {
            int f   = tid + 128 * q;
            int row = f >> 5;
            int c4  = (f & 31) * 4;
            *(float4*)&sP[row][c4] = *(const float4*)&g_PR[0][kk + row][c4];
            *(float4*)&sR[row][c4] = *(const float4*)&g_PR[1][kk + row][c4];
        }
        __syncthreads();

        #pragma unroll 4
        for (int r = 0; r < 16; r++) {
            u64 qr[4], qi[4], nq[4];
            #pragma unroll
            for (int i = 0; i < 4; i++) {
                qr[i] = *(const u64*)&sQrD[r][ty * 4 + i];
                qi[i] = *(const u64*)&sQiD[r][ty * 4 + i];
                nq[i] = *(const u64*)&sNQD[r][ty * 4 + i];
            }
            ulonglong2 pa = *(const ulonglong2*)&sP[r][tx * 8];
            ulonglong2 pb = *(const ulonglong2*)&sP[r][tx * 8 + 4];
            ulonglong2 ra = *(const ulonglong2*)&sR[r][tx * 8];
            ulonglong2 rb = *(const ulonglong2*)&sR[r][tx * 8 + 4];
            u64 p[4] = {pa.x, pa.y, pb.x, pb.y};
            u64 rr[4] = {ra.x, ra.y, rb.x, rb.y};
            #pragma unroll
            for (int i = 0; i < 4; i++)
                #pragma unroll
                for (int j = 0; j < 4; j++) {
                    fma2(sr[i][j], qr[i], p[j]);
                    fma2(sr[i][j], qi[i], rr[j]);
                    fma2(si[i][j], qi[i], p[j]);
                    fma2(si[i][j], nq[i], rr[j]);
                }
        }
        __syncthreads();
    }

    const long NC = (long)N * 128;
    #pragma unroll
    for (int i = 0; i < 4; i++) {
        int n = n0 + ty * 4 + i;
        if (n >= N) continue;
        long base = (long)n * 128 + tx * 8;
        float4 rea = *(const float4*)(re + base);
        float4 reb = *(const float4*)(re + base + 4);
        float4 ima = *(const float4*)(im + base);
        float4 imb = *(const float4*)(im + base + 4);
        float2 s0 = unpk(sr[i][0]), s1 = unpk(sr[i][1]), s2 = unpk(sr[i][2]), s3 = unpk(sr[i][3]);
        float2 t0 = unpk(si[i][0]), t1 = unpk(si[i][1]), t2 = unpk(si[i][2]), t3 = unpk(si[i][3]);
        float srv[8] = {s0.x, s0.y, s1.x, s1.y, s2.x, s2.y, s3.x, s3.y};
        float siv[8] = {t0.x, t0.y, t1.x, t1.y, t2.x, t2.y, t3.x, t3.y};
        float rl[8] = {rea.x, rea.y, rea.z, rea.w, reb.x, reb.y, reb.z, reb.w};
        float il[8] = {ima.x, ima.y, ima.z, ima.w, imb.x, imb.y, imb.z, imb.w};
        float orr[8], oii[8];
        #pragma unroll
        for (int j = 0; j < 8; j++) {
            float mask = (srv[j] >= 0.f) ? 1.f : 0.f;
            orr[j] = rl[j] + mask * srv[j];
            oii[j] = il[j] + mask * siv[j];
        }
        *(float4*)(out + base)          = make_float4(orr[0], orr[1], orr[2], orr[3]);
        *(float4*)(out + base + 4)      = make_float4(orr[4], orr[5], orr[6], orr[7]);
        *(float4*)(out + NC + base)     = make_float4(oii[0], oii[1], oii[2], oii[3]);
        *(float4*)(out + NC + base + 4) = make_float4(oii[4], oii[5], oii[6], oii[7]);
    }
}

// ---------------------------------------------------------------------------
extern "C" void kernel_launch(void* const* d_in, const int* in_sizes, int n_in,
                              void* d_out, int out_size)
{
    const float* real  = (const float*)d_in[0];
    const float* imag  = (const float*)d_in[1];
    const float* Qreal = (const float*)d_in[2];
    const float* Qimag = (const float*)d_in[3];
    const float* Ritz  = (const float*)d_in[4];
    const float* W     = (const float*)d_in[5];
    const int*   ldp   = (const int*)d_in[6];
    float* out = (float*)d_out;

    int N = in_sizes[0] / CDIM;
    int nsplit = (N + 63) / 64;   // 157 for N=10000

    k1_partial<<<dim3(nsplit, 2), dim3(16, 16)>>>(Qreal, Qimag, real, imag, N);
    k2a_reduce<<<512, 256>>>(Ritz, ldp, nsplit);
    k2b_pr<<<dim3(2, 2), dim3(16, 16)>>>(W);
    k3_out<<<(N + 31) / 32, dim3(16, 8)>>>(Qreal, Qimag, real, imag, out, N);
}

// round 6
// speedup vs baseline: 2.2673x; 1.3960x over previous
#include <cuda_runtime.h>

#define KDIM 64
#define CDIM 128
#define MAXSPLIT 160

__device__ float g_part[2][MAXSPLIT][KDIM][CDIM];   // ~10.3 MB used
__device__ float g_UV[2][KDIM][CDIM];
__device__ float g_PR[2][KDIM][CDIM];

typedef unsigned long long u64;

__device__ __forceinline__ void fma2(u64& d, u64 a, u64 b) {
    asm("fma.rn.f32x2 %0, %1, %2, %0;" : "+l"(d) : "l"(a), "l"(b));
}
__device__ __forceinline__ u64 pack2(float x) {
    u64 d; asm("mov.b64 %0, {%1, %1};" : "=l"(d) : "f"(x)); return d;
}
__device__ __forceinline__ u64 neg2(u64 v) { return v ^ 0x8000000080000000ULL; }
__device__ __forceinline__ float2 unpk(u64 v) {
    float2 f; asm("mov.b64 {%0, %1}, %2;" : "=f"(f.x), "=f"(f.y) : "l"(v)); return f;
}

// ---------------------------------------------------------------------------
// Kernel 1: partial U/V over a 64-row slice of N (two 32-row chunks).
//   U[k,c] = sum_n Qr[n,k]*re[n,c] + Qi[n,k]*im[n,c]
//   V[k,c] = sum_n Qi[n,k]*re[n,c] - Qr[n,k]*im[n,c]
// grid (157, 2 c-halves), block (16,16).
// Thread: 4 k (ty*4+i) x 2 c-pairs {c0+tx*2, c0+tx*2+32}. Acc packed over c.
// Q side: LDS.128 broadcast + mov.b64 packs. X side: native float2, stride-2
// lane mapping -> conflict-free.
// ---------------------------------------------------------------------------
__global__ __launch_bounds__(256, 2) void k1_partial(
    const float* __restrict__ Qr, const float* __restrict__ Qi,
    const float* __restrict__ re, const float* __restrict__ im, int N)
{
    __shared__ float sQr[32][64];
    __shared__ float sQi[32][64];
    __shared__ float sRe[32][64];
    __shared__ float sIm[32][64];

    const int s  = blockIdx.x;
    const int c0 = blockIdx.y * 64;
    const int tx = threadIdx.x, ty = threadIdx.y;
    const int tid = ty * 16 + tx;
    const float4 z4 = make_float4(0.f, 0.f, 0.f, 0.f);

    u64 u[4][2] = {};   // [k][c-pair]
    u64 v[4][2] = {};

    for (int rt = 0; rt < 64; rt += 32) {
        const int nb = s * 64 + rt;
        // Q tiles: 32 rows x 64 k = 512 float4 per array (2 passes)
        #pragma unroll
        for (int q = 0; q < 2; q++) {
            int f   = tid + 256 * q;
            int row = f >> 4;
            int k4  = (f & 15) * 4;
            int n   = nb + row;
            float4 a = z4, b = z4;
            if (n < N) {
                a = *(const float4*)(Qr + (long)n * 64 + k4);
                b = *(const float4*)(Qi + (long)n * 64 + k4);
            }
            *(float4*)&sQr[row][k4] = a;
            *(float4*)&sQi[row][k4] = b;
        }
        // X tiles: 32 rows x 64 c-half = 512 float4 per array (2 passes)
        #pragma unroll
        for (int q = 0; q < 2; q++) {
            int f   = tid + 256 * q;
            int row = f >> 4;
            int c4  = (f & 15) * 4;
            int n   = nb + row;
            float4 x = z4, y = z4;
            if (n < N) {
                x = *(const float4*)(re + (long)n * 128 + c0 + c4);
                y = *(const float4*)(im + (long)n * 128 + c0 + c4);
            }
            *(float4*)&sRe[row][c4] = x;
            *(float4*)&sIm[row][c4] = y;
        }
        __syncthreads();

        #pragma unroll 4
        for (int r = 0; r < 32; r++) {
            float4 qr4 = *(const float4*)&sQr[r][ty * 4];   // broadcast
            float4 qi4 = *(const float4*)&sQi[r][ty * 4];
            u64 qr[4] = {pack2(qr4.x), pack2(qr4.y), pack2(qr4.z), pack2(qr4.w)};
            u64 qi[4] = {pack2(qi4.x), pack2(qi4.y), pack2(qi4.z), pack2(qi4.w)};
            u64 nq[4] = {neg2(qr[0]), neg2(qr[1]), neg2(qr[2]), neg2(qr[3])};
            u64 xr[2] = {*(const u64*)&sRe[r][tx * 2], *(const u64*)&sRe[r][tx * 2 + 32]};
            u64 xi[2] = {*(const u64*)&sIm[r][tx * 2], *(const u64*)&sIm[r][tx * 2 + 32]};
            #pragma unroll
            for (int i = 0; i < 4; i++)
                #pragma unroll
                for (int j = 0; j < 2; j++) {
                    fma2(u[i][j], qr[i], xr[j]);
                    fma2(u[i][j], qi[i], xi[j]);
                    fma2(v[i][j], qi[i], xr[j]);
                    fma2(v[i][j], nq[i], xi[j]);
                }
        }
        __syncthreads();
    }

    #pragma unroll
    for (int i = 0; i < 4; i++) {
        int k = ty * 4 + i;
        #pragma unroll
        for (int j = 0; j < 2; j++) {
            int c = c0 + tx * 2 + 32 * j;
            *(float2*)&g_part[0][s][k][c] = unpk(u[i][j]);
            *(float2*)&g_part[1][s][k][c] = unpk(v[i][j]);
        }
    }
}

// ---------------------------------------------------------------------------
// Kernel 2a: reduce partials over splits (8-way parallel per output),
// scale row k by TT = Ritz[k]^long_diff.  grid 512, block 256.
// ---------------------------------------------------------------------------
__global__ __launch_bounds__(256) void k2a_reduce(
    const float* __restrict__ Ritz, const int* __restrict__ ldp, int nsplit)
{
    __shared__ float red[256];
    const int o   = threadIdx.x & 31;
    const int seg = threadIdx.x >> 5;
    const int t   = blockIdx.x * 32 + o;       // 0..16383
    const int uv  = t >> 13;
    const int rem = t & 8191;

    const float* p = &g_part[uv][0][0][0] + rem;
    float sum = 0.f;
    for (int s2 = seg; s2 < nsplit; s2 += 8) sum += p[(long)s2 * 8192];
    red[threadIdx.x] = sum;
    __syncthreads();

    if (threadIdx.x < 32) {
        #pragma unroll
        for (int g = 1; g < 8; g++) sum += red[g * 32 + o];
        int k = rem >> 7;
        int ld = *ldp;
        float rz = Ritz[k];
        float tt = 1.f;
        for (int i = 0; i < ld; i++) tt *= rz;
        (&g_UV[0][0][0])[t] = tt * sum;
    }
}

// ---------------------------------------------------------------------------
// Kernel 2b: P = U' @ W, R = V' @ W   ([64,128] @ [128,128])
// ---------------------------------------------------------------------------
__global__ __launch_bounds__(256) void k2b_pr(const float* __restrict__ W)
{
    __shared__ float sA[64 * 68];
    __shared__ float sW[64 * 64];

    const int m   = blockIdx.x;
    const int cp0 = blockIdx.y * 64;
    const int tx = threadIdx.x, ty = threadIdx.y;
    const int tid = ty * 16 + tx;

    float acc[4][4] = {};

    for (int cc = 0; cc < 128; cc += 64) {
        #pragma unroll
        for (int q = 0; q < 4; q++) {
            int f   = tid + 256 * q;
            int row = f >> 4;
            int c4  = (f & 15) * 4;
            *(float4*)&sA[row * 68 + c4] = *(const float4*)&g_UV[m][row][cc + c4];
            *(float4*)&sW[row * 64 + c4] = *(const float4*)(W + (cc + row) * 128 + cp0 + c4);
        }
        __syncthreads();

        #pragma unroll 4
        for (int r = 0; r < 64; r++) {
            float a[4];
            #pragma unroll
            for (int i = 0; i < 4; i++) a[i] = sA[(ty * 4 + i) * 68 + r];
            float4 w4 = *(float4*)&sW[r * 64 + tx * 4];
            float wj[4] = {w4.x, w4.y, w4.z, w4.w};
            #pragma unroll
            for (int i = 0; i < 4; i++)
                #pragma unroll
                for (int j = 0; j < 4; j++)
                    acc[i][j] += a[i] * wj[j];
        }
        __syncthreads();
    }

    #pragma unroll
    for (int i = 0; i < 4; i++)
        *(float4*)&g_PR[m][ty * 4 + i][cp0 + tx * 4] =
            make_float4(acc[i][0], acc[i][1], acc[i][2], acc[i][3]);
}

// ---------------------------------------------------------------------------
// Kernel 3: res_real = Qr@P + Qi@R, res_imag = Qi@P - Qr@R, masked-ReLU add.
// grid (313, 2 c-halves), block (16,8): 32 rows x 64 cols per CTA.
// Thread: 4 rows (ty*4+i) x 2 c-pairs {c0+tx*2, c0+tx*2+32}. Acc packed over c.
// Q smem stored [k][n] -> LDS.128 broadcast of 4 rows; P/R native float2,
// stride-2 lane mapping -> conflict-free.
// ---------------------------------------------------------------------------
__global__ __launch_bounds__(128) void k3_out(
    const float* __restrict__ Qr, const float* __restrict__ Qi,
    const float* __restrict__ re, const float* __restrict__ im,
    float* __restrict__ out, int N)
{
    __shared__ float sQr[16][32];   // [k-chunk][n-local]
    __shared__ float sQi[16][32];
    __shared__ float sP[16][64];
    __shared__ float sR[16][64];

    const int n0 = blockIdx.x * 32;
    const int c0 = blockIdx.y * 64;
    const int tx = threadIdx.x, ty = threadIdx.y;
    const int tid = ty * 16 + tx;     // 0..127
    const float4 z4 = make_float4(0.f, 0.f, 0.f, 0.f);

    u64 sr[4][2] = {};   // [row][c-pair]
    u64 si[4][2] = {};

    for (int kk = 0; kk < 64; kk += 16) {
        // Q tiles: 32 rows x 16 k, transposed into [k][n]; 1 float4/thread/array
        {
            int row = tid >> 2;           // n-local
            int k4  = (tid & 3) * 4;
            int n   = n0 + row;
            float4 a = z4, b = z4;
            if (n < N) {
                a = *(const float4*)(Qr + (long)n * 64 + kk + k4);
                b = *(const float4*)(Qi + (long)n * 64 + kk + k4);
            }
            sQr[k4 + 0][row] = a.x;  sQr[k4 + 1][row] = a.y;
            sQr[k4 + 2][row] = a.z;  sQr[k4 + 3][row] = a.w;
            sQi[k4 + 0][row] = b.x;  sQi[k4 + 1][row] = b.y;
            sQi[k4 + 2][row] = b.z;  sQi[k4 + 3][row] = b.w;
        }
        // P/R tiles: 16 k x 64 c-half = 256 float4 per array (2 passes)
        #pragma unroll
        for (int q = 0; q < 2; q++) {
            int f   = tid + 128 * q;
            int row = f >> 4;
            int c4  = (f & 15) * 4;
            *(float4*)&sP[row][c4] = *(const float4*)&g_PR[0][kk + row][c0 + c4];
            *(float4*)&sR[row][c4] = *(const float4*)&g_PR[1][kk + row][c0 + c4];
        }
        __syncthreads();

        #pragma unroll 4
        for (int r = 0; r < 16; r++) {
            float4 qr4 = *(const float4*)&sQr[r][ty * 4];   // broadcast: 4 n-rows
            float4 qi4 = *(const float4*)&sQi[r][ty * 4];
            u64 qr[4] = {pack2(qr4.x), pack2(qr4.y), pack2(qr4.z), pack2(qr4.w)};
            u64 qi[4] = {pack2(qi4.x), pack2(qi4.y), pack2(qi4.z), pack2(qi4.w)};
            u64 nq[4] = {neg2(qr[0]), neg2(qr[1]), neg2(qr[2]), neg2(qr[3])};
            u64 p[2]  = {*(const u64*)&sP[r][tx * 2], *(const u64*)&sP[r][tx * 2 + 32]};
            u64 rr[2] = {*(const u64*)&sR[r][tx * 2], *(const u64*)&sR[r][tx * 2 + 32]};
            #pragma unroll
            for (int i = 0; i < 4; i++)
                #pragma unroll
                for (int j = 0; j < 2; j++) {
                    fma2(sr[i][j], qr[i], p[j]);
                    fma2(sr[i][j], qi[i], rr[j]);
                    fma2(si[i][j], qi[i], p[j]);
                    fma2(si[i][j], nq[i], rr[j]);
                }
        }
        __syncthreads();
    }

    const long NC = (long)N * 128;
    #pragma unroll
    for (int i = 0; i < 4; i++) {
        int n = n0 + ty * 4 + i;
        if (n >= N) continue;
        #pragma unroll
        for (int j = 0; j < 2; j++) {
            long base = (long)n * 128 + c0 + tx * 2 + 32 * j;
            float2 rl = *(const float2*)(re + base);
            float2 il = *(const float2*)(im + base);
            float2 sv = unpk(sr[i][j]);
            float2 tv = unpk(si[i][j]);
            float m0 = (sv.x >= 0.f) ? 1.f : 0.f;
            float m1 = (sv.y >= 0.f) ? 1.f : 0.f;
            float2 orr = make_float2(rl.x + m0 * sv.x, rl.y + m1 * sv.y);
            float2 oii = make_float2(il.x + m0 * tv.x, il.y + m1 * tv.y);
            *(float2*)(out + base)      = orr;
            *(float2*)(out + NC + base) = oii;
        }
    }
}

// ---------------------------------------------------------------------------
extern "C" void kernel_launch(void* const* d_in, const int* in_sizes, int n_in,
                              void* d_out, int out_size)
{
    const float* real  = (const float*)d_in[0];
    const float* imag  = (const float*)d_in[1];
    const float* Qreal = (const float*)d_in[2];
    const float* Qimag = (const float*)d_in[3];
    const float* Ritz  = (const float*)d_in[4];
    const float* W     = (const float*)d_in[5];
    const int*   ldp   = (const int*)d_in[6];
    float* out = (float*)d_out;

    int N = in_sizes[0] / CDIM;
    int nsplit = (N + 63) / 64;   // 157 for N=10000

    k1_partial<<<dim3(nsplit, 2), dim3(16, 16)>>>(Qreal, Qimag, real, imag, N);
    k2a_reduce<<<512, 256>>>(Ritz, ldp, nsplit);
    k2b_pr<<<dim3(2, 2), dim3(16, 16)>>>(W);
    k3_out<<<dim3((N + 31) / 32, 2), dim3(16, 8)>>>(Qreal, Qimag, real, imag, out, N);
}

// round 7
// speedup vs baseline: 2.2772x; 1.0044x over previous
#include <cuda_runtime.h>

#define KDIM 64
#define CDIM 128
#define MAXSPLIT 160

__device__ float g_part[2][MAXSPLIT][KDIM][CDIM];   // ~10.3 MB used
__device__ float g_UV[2][KDIM][CDIM];
__device__ float g_PR[2][KDIM][CDIM];

typedef unsigned long long u64;

__device__ __forceinline__ void fma2(u64& d, u64 a, u64 b) {
    asm("fma.rn.f32x2 %0, %1, %2, %0;" : "+l"(d) : "l"(a), "l"(b));
}
__device__ __forceinline__ u64 pack2(float x) {
    u64 d; asm("mov.b64 %0, {%1, %1};" : "=l"(d) : "f"(x)); return d;
}
__device__ __forceinline__ u64 neg2(u64 v) { return v ^ 0x8000000080000000ULL; }
__device__ __forceinline__ float2 unpk(u64 v) {
    float2 f; asm("mov.b64 {%0, %1}, %2;" : "=f"(f.x), "=f"(f.y) : "l"(v)); return f;
}
__device__ __forceinline__ void cpa16(void* s, const void* g) {
    unsigned sa = (unsigned)__cvta_generic_to_shared(s);
    asm volatile("cp.async.cg.shared.global [%0], [%1], 16;" :: "r"(sa), "l"(g));
}
__device__ __forceinline__ void cpa_commit() {
    asm volatile("cp.async.commit_group;" ::: "memory");
}
template<int NN> __device__ __forceinline__ void cpa_wait() {
    asm volatile("cp.async.wait_group %0;" :: "n"(NN) : "memory");
}

// ---------------------------------------------------------------------------
// Kernel 1: partial U/V over a 64-row slice of N, cp.async double-buffered
// 16-row stages.
//   U[k,c] = sum_n Qr[n,k]*re[n,c] + Qi[n,k]*im[n,c]
//   V[k,c] = sum_n Qi[n,k]*re[n,c] - Qr[n,k]*im[n,c]
// grid (157, 2 c-halves), block (16,16).
// Thread: 4 k (ty*4+i) x 2 c-pairs {c0+tx*2, c0+tx*2+32}, acc packed over c.
// ---------------------------------------------------------------------------
#define CH 16
__global__ __launch_bounds__(256, 2) void k1_partial(
    const float* __restrict__ Qr, const float* __restrict__ Qi,
    const float* __restrict__ re, const float* __restrict__ im, int N)
{
    __shared__ float sQr[2][CH][64];
    __shared__ float sQi[2][CH][64];
    __shared__ float sRe[2][CH][64];
    __shared__ float sIm[2][CH][64];

    const int s  = blockIdx.x;
    const int c0 = blockIdx.y * 64;
    const int n0 = s * 64;
    const int tx = threadIdx.x, ty = threadIdx.y;
    const int tid = ty * 16 + tx;
    const int lrow = tid >> 4;          // 0..15
    const int lc4  = (tid & 15) * 4;    // 0..60
    const float4 z4 = make_float4(0.f, 0.f, 0.f, 0.f);

    u64 u[4][2] = {};
    u64 v[4][2] = {};

    // stage issue: one float4 per thread per array
    auto issue = [&](int t, int buf) {
        int n = n0 + t * CH + lrow;
        if (n < N) {
            cpa16(&sQr[buf][lrow][lc4], Qr + (long)n * 64 + lc4);
            cpa16(&sQi[buf][lrow][lc4], Qi + (long)n * 64 + lc4);
            cpa16(&sRe[buf][lrow][lc4], re + (long)n * 128 + c0 + lc4);
            cpa16(&sIm[buf][lrow][lc4], im + (long)n * 128 + c0 + lc4);
        } else {
            *(float4*)&sQr[buf][lrow][lc4] = z4;
            *(float4*)&sQi[buf][lrow][lc4] = z4;
            *(float4*)&sRe[buf][lrow][lc4] = z4;
            *(float4*)&sIm[buf][lrow][lc4] = z4;
        }
    };

    issue(0, 0);
    cpa_commit();

    #pragma unroll
    for (int t = 0; t < 4; t++) {
        const int buf = t & 1;
        if (t < 3) { issue(t + 1, buf ^ 1); cpa_commit(); cpa_wait<1>(); }
        else       { cpa_wait<0>(); }
        __syncthreads();

        #pragma unroll 8
        for (int r = 0; r < CH; r++) {
            float4 qr4 = *(const float4*)&sQr[buf][r][ty * 4];   // broadcast
            float4 qi4 = *(const float4*)&sQi[buf][r][ty * 4];
            u64 qr[4] = {pack2(qr4.x), pack2(qr4.y), pack2(qr4.z), pack2(qr4.w)};
            u64 qi[4] = {pack2(qi4.x), pack2(qi4.y), pack2(qi4.z), pack2(qi4.w)};
            u64 nq[4] = {neg2(qr[0]), neg2(qr[1]), neg2(qr[2]), neg2(qr[3])};
            u64 xr[2] = {*(const u64*)&sRe[buf][r][tx * 2],
                         *(const u64*)&sRe[buf][r][tx * 2 + 32]};
            u64 xi[2] = {*(const u64*)&sIm[buf][r][tx * 2],
                         *(const u64*)&sIm[buf][r][tx * 2 + 32]};
            #pragma unroll
            for (int i = 0; i < 4; i++)
                #pragma unroll
                for (int j = 0; j < 2; j++) {
                    fma2(u[i][j], qr[i], xr[j]);
                    fma2(u[i][j], qi[i], xi[j]);
                    fma2(v[i][j], qi[i], xr[j]);
                    fma2(v[i][j], nq[i], xi[j]);
                }
        }
        __syncthreads();
    }

    #pragma unroll
    for (int i = 0; i < 4; i++) {
        int k = ty * 4 + i;
        #pragma unroll
        for (int j = 0; j < 2; j++) {
            int c = c0 + tx * 2 + 32 * j;
            *(float2*)&g_part[0][s][k][c] = unpk(u[i][j]);
            *(float2*)&g_part[1][s][k][c] = unpk(v[i][j]);
        }
    }
}

// ---------------------------------------------------------------------------
// Kernel 2a: reduce partials over splits (8-way parallel per output),
// scale row k by TT = Ritz[k]^long_diff.  grid 512, block 256.
// ---------------------------------------------------------------------------
__global__ __launch_bounds__(256) void k2a_reduce(
    const float* __restrict__ Ritz, const int* __restrict__ ldp, int nsplit)
{
    __shared__ float red[256];
    const int o   = threadIdx.x & 31;
    const int seg = threadIdx.x >> 5;
    const int t   = blockIdx.x * 32 + o;       // 0..16383
    const int uv  = t >> 13;
    const int rem = t & 8191;

    const float* p = &g_part[uv][0][0][0] + rem;
    float sum = 0.f;
    for (int s2 = seg; s2 < nsplit; s2 += 8) sum += p[(long)s2 * 8192];
    red[threadIdx.x] = sum;
    __syncthreads();

    if (threadIdx.x < 32) {
        #pragma unroll
        for (int g = 1; g < 8; g++) sum += red[g * 32 + o];
        int k = rem >> 7;
        int ld = *ldp;
        float rz = Ritz[k];
        float tt = 1.f;
        for (int i = 0; i < ld; i++) tt *= rz;
        (&g_UV[0][0][0])[t] = tt * sum;
    }
}

// ---------------------------------------------------------------------------
// Kernel 2b: P = U' @ W, R = V' @ W   ([64,128] @ [128,128])
// ---------------------------------------------------------------------------
__global__ __launch_bounds__(256) void k2b_pr(const float* __restrict__ W)
{
    __shared__ float sA[64 * 68];
    __shared__ float sW[64 * 64];

    const int m   = blockIdx.x;
    const int cp0 = blockIdx.y * 64;
    const int tx = threadIdx.x, ty = threadIdx.y;
    const int tid = ty * 16 + tx;

    float acc[4][4] = {};

    for (int cc = 0; cc < 128; cc += 64) {
        #pragma unroll
        for (int q = 0; q < 4; q++) {
            int f   = tid + 256 * q;
            int row = f >> 4;
            int c4  = (f & 15) * 4;
            *(float4*)&sA[row * 68 + c4] = *(const float4*)&g_UV[m][row][cc + c4];
            *(float4*)&sW[row * 64 + c4] = *(const float4*)(W + (cc + row) * 128 + cp0 + c4);
        }
        __syncthreads();

        #pragma unroll 4
        for (int r = 0; r < 64; r++) {
            float a[4];
            #pragma unroll
            for (int i = 0; i < 4; i++) a[i] = sA[(ty * 4 + i) * 68 + r];
            float4 w4 = *(float4*)&sW[r * 64 + tx * 4];
            float wj[4] = {w4.x, w4.y, w4.z, w4.w};
            #pragma unroll
            for (int i = 0; i < 4; i++)
                #pragma unroll
                for (int j = 0; j < 4; j++)
                    acc[i][j] += a[i] * wj[j];
        }
        __syncthreads();
    }

    #pragma unroll
    for (int i = 0; i < 4; i++)
        *(float4*)&g_PR[m][ty * 4 + i][cp0 + tx * 4] =
            make_float4(acc[i][0], acc[i][1], acc[i][2], acc[i][3]);
}

// ---------------------------------------------------------------------------
// Kernel 3: res_real = Qr@P + Qi@R, res_imag = Qi@P - Qr@R, masked-ReLU add.
// grid (313, 2 c-halves), block (16,8): 32 rows x 64 cols per CTA.
// Single load phase (whole K=64 resident: Q transposed [k][n], P/R [k][c]),
// one __syncthreads, 64-deep unrolled MAC loop. Epilogue re/im prefetched
// into registers before the loop.
// ---------------------------------------------------------------------------
__global__ __launch_bounds__(128) void k3_out(
    const float* __restrict__ Qr, const float* __restrict__ Qi,
    const float* __restrict__ re, const float* __restrict__ im,
    float* __restrict__ out, int N)
{
    __shared__ float sQr[64][32];   // [k][n-local]  8KB
    __shared__ float sQi[64][32];   //               8KB
    __shared__ float sP[64][64];    // [k][c-half]  16KB
    __shared__ float sR[64][64];    //              16KB   = 48KB total

    const int n0 = blockIdx.x * 32;
    const int c0 = blockIdx.y * 64;
    const int tx = threadIdx.x, ty = threadIdx.y;
    const int tid = ty * 16 + tx;     // 0..127
    const float4 z4 = make_float4(0.f, 0.f, 0.f, 0.f);

    // ---- Load Q (transposed) : 32 rows x 64 k = 512 float4 over 128 thr ----
    #pragma unroll
    for (int q = 0; q < 4; q++) {
        int f   = tid + 128 * q;
        int row = f >> 4;             // n-local 0..31
        int k4  = (f & 15) * 4;       // 0..60
        int n   = n0 + row;
        float4 a = z4, b = z4;
        if (n < N) {
            a = *(const float4*)(Qr + (long)n * 64 + k4);
            b = *(const float4*)(Qi + (long)n * 64 + k4);
        }
        sQr[k4 + 0][row] = a.x;  sQr[k4 + 1][row] = a.y;
        sQr[k4 + 2][row] = a.z;  sQr[k4 + 3][row] = a.w;
        sQi[k4 + 0][row] = b.x;  sQi[k4 + 1][row] = b.y;
        sQi[k4 + 2][row] = b.z;  sQi[k4 + 3][row] = b.w;
    }
    // ---- Load P/R : 64 k x 64 c-half = 1024 float4 each over 128 thr ----
    #pragma unroll
    for (int q = 0; q < 8; q++) {
        int f   = tid + 128 * q;
        int row = f >> 4;
        int c4  = (f & 15) * 4;
        *(float4*)&sP[row][c4] = *(const float4*)&g_PR[0][row][c0 + c4];
        *(float4*)&sR[row][c4] = *(const float4*)&g_PR[1][row][c0 + c4];
    }

    // ---- Prefetch epilogue re/im into registers (latency hidden by MACs) ----
    const long NC = (long)N * 128;
    float2 rl[4][2], il[4][2];
    #pragma unroll
    for (int i = 0; i < 4; i++) {
        int n = n0 + ty * 4 + i;
        bool ok = (n < N);
        #pragma unroll
        for (int j = 0; j < 2; j++) {
            long base = (long)n * 128 + c0 + tx * 2 + 32 * j;
            rl[i][j] = ok ? *(const float2*)(re + base) : make_float2(0.f, 0.f);
            il[i][j] = ok ? *(const float2*)(im + base) : make_float2(0.f, 0.f);
        }
    }

    __syncthreads();

    u64 sr[4][2] = {};
    u64 si[4][2] = {};

    #pragma unroll 8
    for (int r = 0; r < 64; r++) {
        float4 qr4 = *(const float4*)&sQr[r][ty * 4];   // broadcast (4 n-rows)
        float4 qi4 = *(const float4*)&sQi[r][ty * 4];
        u64 qr[4] = {pack2(qr4.x), pack2(qr4.y), pack2(qr4.z), pack2(qr4.w)};
        u64 qi[4] = {pack2(qi4.x), pack2(qi4.y), pack2(qi4.z), pack2(qi4.w)};
        u64 nq[4] = {neg2(qr[0]), neg2(qr[1]), neg2(qr[2]), neg2(qr[3])};
        u64 p[2]  = {*(const u64*)&sP[r][tx * 2], *(const u64*)&sP[r][tx * 2 + 32]};
        u64 rr[2] = {*(const u64*)&sR[r][tx * 2], *(const u64*)&sR[r][tx * 2 + 32]};
        #pragma unroll
        for (int i = 0; i < 4; i++)
            #pragma unroll
            for (int j = 0; j < 2; j++) {
                fma2(sr[i][j], qr[i], p[j]);
                fma2(sr[i][j], qi[i], rr[j]);
                fma2(si[i][j], qi[i], p[j]);
                fma2(si[i][j], nq[i], rr[j]);
            }
    }

    #pragma unroll
    for (int i = 0; i < 4; i++) {
        int n = n0 + ty * 4 + i;
        if (n >= N) continue;
        #pragma unroll
        for (int j = 0; j < 2; j++) {
            long base = (long)n * 128 + c0 + tx * 2 + 32 * j;
            float2 sv = unpk(sr[i][j]);
            float2 tv = unpk(si[i][j]);
            float m0 = (sv.x >= 0.f) ? 1.f : 0.f;
            float m1 = (sv.y >= 0.f) ? 1.f : 0.f;
            float2 orr = make_float2(rl[i][j].x + m0 * sv.x, rl[i][j].y + m1 * sv.y);
            float2 oii = make_float2(il[i][j].x + m0 * tv.x, il[i][j].y + m1 * tv.y);
            *(float2*)(out + base)      = orr;
            *(float2*)(out + NC + base) = oii;
        }
    }
}

// ---------------------------------------------------------------------------
extern "C" void kernel_launch(void* const* d_in, const int* in_sizes, int n_in,
                              void* d_out, int out_size)
{
    const float* real  = (const float*)d_in[0];
    const float* imag  = (const float*)d_in[1];
    const float* Qreal = (const float*)d_in[2];
    const float* Qimag = (const float*)d_in[3];
    const float* Ritz  = (const float*)d_in[4];
    const float* W     = (const float*)d_in[5];
    const int*   ldp   = (const int*)d_in[6];
    float* out = (float*)d_out;

    int N = in_sizes[0] / CDIM;
    int nsplit = (N + 63) / 64;   // 157 for N=10000

    k1_partial<<<dim3(nsplit, 2), dim3(16, 16)>>>(Qreal, Qimag, real, imag, N);
    k2a_reduce<<<512, 256>>>(Ritz, ldp, nsplit);
    k2b_pr<<<dim3(2, 2), dim3(16, 16)>>>(W);
    k3_out<<<dim3((N + 31) / 32, 2), dim3(16, 8)>>>(Qreal, Qimag, real, imag, out, N);
}

// round 8
// speedup vs baseline: 2.9740x; 1.3060x over previous
#include <cuda_runtime.h>
#include <cuda_bf16.h>
#include <cstdint>

#define CDIM 128
#define MAXSPLIT 320
#define PQ 72   // bf16 tile pitch: 144B = 16B-aligned rows, conflict-free LDSM

__device__ float g_part[2][MAXSPLIT][64][CDIM];   // ~21 MB
__device__ float g_UV[2][64][CDIM];
__device__ unsigned short g_Ph[64][128], g_Pl[64][128];
__device__ unsigned short g_Rh[64][128], g_Rl[64][128];

// ---------------------------------------------------------------------------
// helpers
// ---------------------------------------------------------------------------
__device__ __forceinline__ unsigned sadr(const void* p) {
    return (unsigned)__cvta_generic_to_shared(p);
}
// pack two fp32 -> bf16x2 (x0 in low half = lower address)
__device__ __forceinline__ uint32_t pk2(float x0, float x1) {
    uint32_t d;
    asm("cvt.rn.bf16x2.f32 %0, %2, %1;" : "=r"(d) : "f"(x0), "f"(x1));
    return d;
}
__device__ __forceinline__ float bfr(float x) {   // round-trip through bf16
    return __bfloat162float(__float2bfloat16(x));
}
// convert float4 -> hi/lo bf16x2 pairs, store 8B each
__device__ __forceinline__ void cvst(unsigned short* hp, unsigned short* lp, float4 a) {
    ((uint32_t*)hp)[0] = pk2(a.x, a.y);
    ((uint32_t*)hp)[1] = pk2(a.z, a.w);
    float l0 = a.x - bfr(a.x), l1 = a.y - bfr(a.y);
    float l2 = a.z - bfr(a.z), l3 = a.w - bfr(a.w);
    ((uint32_t*)lp)[0] = pk2(l0, l1);
    ((uint32_t*)lp)[1] = pk2(l2, l3);
}
__device__ __forceinline__ void ldmA(uint32_t* a, unsigned addr) {   // x4 non-trans
    asm volatile("ldmatrix.sync.aligned.m8n8.x4.shared.b16 {%0,%1,%2,%3},[%4];"
        : "=r"(a[0]), "=r"(a[1]), "=r"(a[2]), "=r"(a[3]) : "r"(addr));
}
__device__ __forceinline__ void ldmAT(uint32_t* a, unsigned addr) {  // x4 trans
    asm volatile("ldmatrix.sync.aligned.m8n8.x4.trans.shared.b16 {%0,%1,%2,%3},[%4];"
        : "=r"(a[0]), "=r"(a[1]), "=r"(a[2]), "=r"(a[3]) : "r"(addr));
}
__device__ __forceinline__ void ldmBT(uint32_t* b, unsigned addr) {  // x2 trans
    asm volatile("ldmatrix.sync.aligned.m8n8.x2.trans.shared.b16 {%0,%1},[%2];"
        : "=r"(b[0]), "=r"(b[1]) : "r"(addr));
}
__device__ __forceinline__ void mma(float* d, const uint32_t* a, const uint32_t* b) {
    asm volatile("mma.sync.aligned.m16n8k16.row.col.f32.bf16.bf16.f32 "
        "{%0,%1,%2,%3},{%4,%5,%6,%7},{%8,%9},{%0,%1,%2,%3};"
        : "+f"(d[0]), "+f"(d[1]), "+f"(d[2]), "+f"(d[3])
        : "r"(a[0]), "r"(a[1]), "r"(a[2]), "r"(a[3]), "r"(b[0]), "r"(b[1]));
}
#define NEG4(dst, src) { dst[0]=src[0]^0x80008000u; dst[1]=src[1]^0x80008000u; \
                         dst[2]=src[2]^0x80008000u; dst[3]=src[3]^0x80008000u; }

// ---------------------------------------------------------------------------
// Kernel 1: partial U/V over a 32-row slice of N (MMA, bf16 hi/lo 3-pass).
//   U = Qr^T re + Qi^T im ;  V = Qi^T re - Qr^T im     (per n-slice, per c-half)
// grid (nsplit, 2 c-halves), block 128 (4 warps = 4 k-slabs of 16).
// A = Q^T via ldmatrix.x4.trans; B = X via ldmatrix.x2.trans.
// ---------------------------------------------------------------------------
__global__ __launch_bounds__(128) void k1_partial(
    const float* __restrict__ Qr, const float* __restrict__ Qi,
    const float* __restrict__ re, const float* __restrict__ im, int N)
{
    __shared__ unsigned short sQrh[32][PQ], sQrl[32][PQ], sQih[32][PQ], sQil[32][PQ];
    __shared__ unsigned short sXrh[32][PQ], sXrl[32][PQ], sXih[32][PQ], sXil[32][PQ];

    const int s  = blockIdx.x;
    const int c0 = blockIdx.y * 64;
    const int nb = s * 32;
    const int tid = threadIdx.x;
    const float4 f4z = make_float4(0.f, 0.f, 0.f, 0.f);

    // load + convert: Q tile [32][64] and X half [32][64] (re,im)
    #pragma unroll
    for (int q = 0; q < 4; q++) {
        int f = tid + 128 * q;
        int row = f >> 4, k4 = (f & 15) * 4;
        int n = nb + row;
        bool ok = (n < N);
        float4 a = ok ? *(const float4*)(Qr + (long)n * 64 + k4) : f4z;
        float4 b = ok ? *(const float4*)(Qi + (long)n * 64 + k4) : f4z;
        cvst(&sQrh[row][k4], &sQrl[row][k4], a);
        cvst(&sQih[row][k4], &sQil[row][k4], b);
        float4 x = ok ? *(const float4*)(re + (long)n * 128 + c0 + k4) : f4z;
        float4 y = ok ? *(const float4*)(im + (long)n * 128 + c0 + k4) : f4z;
        cvst(&sXrh[row][k4], &sXrl[row][k4], x);
        cvst(&sXih[row][k4], &sXil[row][k4], y);
    }
    __syncthreads();

    const int lane = tid & 31, warp = tid >> 5;
    const int m0 = warp * 16;                 // k-spectral slab
    const int r8 = lane & 7, sel = lane >> 3;
    const int atrow = ((sel >> 1) & 1) * 8 + r8;     // A^T quad row (n-dim)
    const int atcol = m0 + (sel & 1) * 8;            // A^T quad col (k-dim)
    const int brow = lane & 15;

    float u[8][4] = {};
    float v[8][4] = {};

    #pragma unroll
    for (int ks = 0; ks < 2; ks++) {
        const int n0 = ks * 16;
        uint32_t qrh[4], qrl[4], qih[4], qil[4], nqh[4], nql[4];
        ldmAT(qrh, sadr(&sQrh[n0 + atrow][atcol]));
        ldmAT(qrl, sadr(&sQrl[n0 + atrow][atcol]));
        ldmAT(qih, sadr(&sQih[n0 + atrow][atcol]));
        ldmAT(qil, sadr(&sQil[n0 + atrow][atcol]));
        NEG4(nqh, qrh);
        NEG4(nql, qrl);
        #pragma unroll
        for (int nt = 0; nt < 8; nt++) {
            uint32_t xh[2], xl[2], yh[2], yl[2];
            ldmBT(xh, sadr(&sXrh[n0 + brow][nt * 8]));
            ldmBT(xl, sadr(&sXrl[n0 + brow][nt * 8]));
            ldmBT(yh, sadr(&sXih[n0 + brow][nt * 8]));
            ldmBT(yl, sadr(&sXil[n0 + brow][nt * 8]));
            mma(u[nt], qrh, xh); mma(u[nt], qrh, xl); mma(u[nt], qrl, xh);
            mma(u[nt], qih, yh); mma(u[nt], qih, yl); mma(u[nt], qil, yh);
            mma(v[nt], qih, xh); mma(v[nt], qih, xl); mma(v[nt], qil, xh);
            mma(v[nt], nqh, yh); mma(v[nt], nqh, yl); mma(v[nt], nql, yh);
        }
    }

    const int gid = lane >> 2, tig = lane & 3;
    #pragma unroll
    for (int nt = 0; nt < 8; nt++) {
        int k = m0 + gid;
        int c = c0 + nt * 8 + tig * 2;
        *(float2*)&g_part[0][s][k][c]     = make_float2(u[nt][0], u[nt][1]);
        *(float2*)&g_part[0][s][k + 8][c] = make_float2(u[nt][2], u[nt][3]);
        *(float2*)&g_part[1][s][k][c]     = make_float2(v[nt][0], v[nt][1]);
        *(float2*)&g_part[1][s][k + 8][c] = make_float2(v[nt][2], v[nt][3]);
    }
}

// ---------------------------------------------------------------------------
// Kernel 2a: reduce partials over splits, scale row k by TT = Ritz[k]^ld.
// ---------------------------------------------------------------------------
__global__ __launch_bounds__(256) void k2a_reduce(
    const float* __restrict__ Ritz, const int* __restrict__ ldp, int nsplit)
{
    __shared__ float red[256];
    const int o   = threadIdx.x & 31;
    const int seg = threadIdx.x >> 5;
    const int t   = blockIdx.x * 32 + o;       // 0..16383
    const int uv  = t >> 13;
    const int rem = t & 8191;

    const float* p = &g_part[uv][0][0][0] + rem;
    float sum = 0.f;
    for (int s2 = seg; s2 < nsplit; s2 += 8) sum += p[(long)s2 * 8192];
    red[threadIdx.x] = sum;
    __syncthreads();

    if (threadIdx.x < 32) {
        #pragma unroll
        for (int g = 1; g < 8; g++) sum += red[g * 32 + o];
        int k = rem >> 7;
        int ld = *ldp;
        float rz = Ritz[k];
        float tt = 1.f;
        for (int i = 0; i < ld; i++) tt *= rz;
        (&g_UV[0][0][0])[t] = tt * sum;
    }
}

// ---------------------------------------------------------------------------
// Kernel 2b: P = U' @ W, R = V' @ W  ([64,128]@[128,128]), fp32 scalar;
// outputs bf16 hi/lo arrays for k3's MMA path.
// ---------------------------------------------------------------------------
__global__ __launch_bounds__(256) void k2b_pr(const float* __restrict__ W)
{
    __shared__ float sA[64 * 68];
    __shared__ float sW[64 * 64];

    const int m   = blockIdx.x;
    const int cp0 = blockIdx.y * 64;
    const int tx = threadIdx.x, ty = threadIdx.y;
    const int tid = ty * 16 + tx;

    float acc[4][4] = {};

    for (int cc = 0; cc < 128; cc += 64) {
        #pragma unroll
        for (int q = 0; q < 4; q++) {
            int f   = tid + 256 * q;
            int row = f >> 4;
            int c4  = (f & 15) * 4;
            *(float4*)&sA[row * 68 + c4] = *(const float4*)&g_UV[m][row][cc + c4];
            *(float4*)&sW[row * 64 + c4] = *(const float4*)(W + (cc + row) * 128 + cp0 + c4);
        }
        __syncthreads();

        #pragma unroll 4
        for (int r = 0; r < 64; r++) {
            float a[4];
            #pragma unroll
            for (int i = 0; i < 4; i++) a[i] = sA[(ty * 4 + i) * 68 + r];
            float4 w4 = *(float4*)&sW[r * 64 + tx * 4];
            float wj[4] = {w4.x, w4.y, w4.z, w4.w};
            #pragma unroll
            for (int i = 0; i < 4; i++)
                #pragma unroll
                for (int j = 0; j < 4; j++)
                    acc[i][j] += a[i] * wj[j];
        }
        __syncthreads();
    }

    unsigned short (*Dh)[128] = (m == 0) ? g_Ph : g_Rh;
    unsigned short (*Dl)[128] = (m == 0) ? g_Pl : g_Rl;
    #pragma unroll
    for (int i = 0; i < 4; i++) {
        int k = ty * 4 + i;
        int c = cp0 + tx * 4;
        ((uint32_t*)&Dh[k][c])[0] = pk2(acc[i][0], acc[i][1]);
        ((uint32_t*)&Dh[k][c])[1] = pk2(acc[i][2], acc[i][3]);
        float l0 = acc[i][0] - bfr(acc[i][0]), l1 = acc[i][1] - bfr(acc[i][1]);
        float l2 = acc[i][2] - bfr(acc[i][2]), l3 = acc[i][3] - bfr(acc[i][3]);
        ((uint32_t*)&Dl[k][c])[0] = pk2(l0, l1);
        ((uint32_t*)&Dl[k][c])[1] = pk2(l2, l3);
    }
}

// ---------------------------------------------------------------------------
// Kernel 3: res_real = Qr@P + Qi@R, res_imag = Qi@P - Qr@R (MMA 3-pass),
// masked-ReLU epilogue. grid (nsplit, 2 c-halves), block 128.
// 4 warps = 2 n-slabs x 2 c-subhalves. P/R loaded in two 32-k phases.
// ---------------------------------------------------------------------------
__global__ __launch_bounds__(128) void k3_out(
    const float* __restrict__ Qr, const float* __restrict__ Qi,
    const float* __restrict__ re, const float* __restrict__ im,
    float* __restrict__ out, int N)
{
    __shared__ unsigned short sQrh[32][PQ], sQrl[32][PQ], sQih[32][PQ], sQil[32][PQ];
    __shared__ unsigned short sPh[32][PQ], sPl[32][PQ], sRh[32][PQ], sRl[32][PQ];

    const int n0 = blockIdx.x * 32;
    const int c0 = blockIdx.y * 64;
    const int tid = threadIdx.x;
    const float4 f4z = make_float4(0.f, 0.f, 0.f, 0.f);

    // load + convert Q tile [32][64]
    #pragma unroll
    for (int q = 0; q < 4; q++) {
        int f = tid + 128 * q;
        int row = f >> 4, k4 = (f & 15) * 4;
        int n = n0 + row;
        bool ok = (n < N);
        float4 a = ok ? *(const float4*)(Qr + (long)n * 64 + k4) : f4z;
        float4 b = ok ? *(const float4*)(Qi + (long)n * 64 + k4) : f4z;
        cvst(&sQrh[row][k4], &sQrl[row][k4], a);
        cvst(&sQih[row][k4], &sQil[row][k4], b);
    }

    const int lane = tid & 31, warp = tid >> 5;
    const int m0 = (warp & 1) * 16;           // n-slab
    const int cs = (warp >> 1) * 32;          // c-subhalf
    const int arow = m0 + (lane & 15);
    const int acol8 = (lane >> 4) * 8;
    const int brow = lane & 15;
    const int gid = lane >> 2, tig = lane & 3;

    float sr[4][4] = {};
    float si[4][4] = {};

    #pragma unroll
    for (int ph = 0; ph < 2; ph++) {
        __syncthreads();    // joins Q-store (ph=0) / protects sP reuse (ph=1)
        const int kk = ph * 32;
        #pragma unroll
        for (int q = 0; q < 8; q++) {
            int f = tid + 128 * q;
            int row = f >> 5, cu = (f & 31);
            *(uint32_t*)&sPh[row][cu * 2] = *(const uint32_t*)&g_Ph[kk + row][c0 + cu * 2];
            *(uint32_t*)&sPl[row][cu * 2] = *(const uint32_t*)&g_Pl[kk + row][c0 + cu * 2];
            *(uint32_t*)&sRh[row][cu * 2] = *(const uint32_t*)&g_Rh[kk + row][c0 + cu * 2];
            *(uint32_t*)&sRl[row][cu * 2] = *(const uint32_t*)&g_Rl[kk + row][c0 + cu * 2];
        }
        __syncthreads();

        #pragma unroll
        for (int ks = 0; ks < 2; ks++) {
            const int k0 = ks * 16;
            uint32_t qrh[4], qrl[4], qih[4], qil[4], nqh[4], nql[4];
            ldmA(qrh, sadr(&sQrh[arow][kk + k0 + acol8]));
            ldmA(qrl, sadr(&sQrl[arow][kk + k0 + acol8]));
            ldmA(qih, sadr(&sQih[arow][kk + k0 + acol8]));
            ldmA(qil, sadr(&sQil[arow][kk + k0 + acol8]));
            NEG4(nqh, qrh);
            NEG4(nql, qrl);
            #pragma unroll
            for (int nt = 0; nt < 4; nt++) {
                uint32_t pf[2], pl[2], rf[2], rl2[2];
                ldmBT(pf,  sadr(&sPh[k0 + brow][cs + nt * 8]));
                ldmBT(pl,  sadr(&sPl[k0 + brow][cs + nt * 8]));
                ldmBT(rf,  sadr(&sRh[k0 + brow][cs + nt * 8]));
                ldmBT(rl2, sadr(&sRl[k0 + brow][cs + nt * 8]));
                mma(sr[nt], qrh, pf);  mma(sr[nt], qrh, pl);  mma(sr[nt], qrl, pf);
                mma(sr[nt], qih, rf);  mma(sr[nt], qih, rl2); mma(sr[nt], qil, rf);
                mma(si[nt], qih, pf);  mma(si[nt], qih, pl);  mma(si[nt], qil, pf);
                mma(si[nt], nqh, rf);  mma(si[nt], nqh, rl2); mma(si[nt], nql, rf);
            }
        }
    }

    // epilogue: masked-ReLU add, write out
    const long NC = (long)N * 128;
    #pragma unroll
    for (int nt = 0; nt < 4; nt++) {
        int c = c0 + cs + nt * 8 + tig * 2;
        int r0 = n0 + m0 + gid;
        int r1 = r0 + 8;
        if (r0 < N) {
            long base = (long)r0 * 128 + c;
            float2 rv = *(const float2*)(re + base);
            float2 iv = *(const float2*)(im + base);
            float mk0 = (sr[nt][0] >= 0.f) ? 1.f : 0.f;
            float mk1 = (sr[nt][1] >= 0.f) ? 1.f : 0.f;
            *(float2*)(out + base)      = make_float2(rv.x + mk0 * sr[nt][0], rv.y + mk1 * sr[nt][1]);
            *(float2*)(out + NC + base) = make_float2(iv.x + mk0 * si[nt][0], iv.y + mk1 * si[nt][1]);
        }
        if (r1 < N) {
            long base = (long)r1 * 128 + c;
            float2 rv = *(const float2*)(re + base);
            float2 iv = *(const float2*)(im + base);
            float mk2 = (sr[nt][2] >= 0.f) ? 1.f : 0.f;
            float mk3 = (sr[nt][3] >= 0.f) ? 1.f : 0.f;
            *(float2*)(out + base)      = make_float2(rv.x + mk2 * sr[nt][2], rv.y + mk3 * sr[nt][3]);
            *(float2*)(out + NC + base) = make_float2(iv.x + mk2 * si[nt][2], iv.y + mk3 * si[nt][3]);
        }
    }
}

// ---------------------------------------------------------------------------
extern "C" void kernel_launch(void* const* d_in, const int* in_sizes, int n_in,
                              void* d_out, int out_size)
{
    const float* real  = (const float*)d_in[0];
    const float* imag  = (const float*)d_in[1];
    const float* Qreal = (const float*)d_in[2];
    const float* Qimag = (const float*)d_in[3];
    const float* Ritz  = (const float*)d_in[4];
    const float* W     = (const float*)d_in[5];
    const int*   ldp   = (const int*)d_in[6];
    float* out = (float*)d_out;

    int N = in_sizes[0] / CDIM;
    int nsplit = (N + 31) / 32;   // 313 for N=10000, fits MAXSPLIT=320

    k1_partial<<<dim3(nsplit, 2), 128>>>(Qreal, Qimag, real, imag, N);
    k2a_reduce<<<512, 256>>>(Ritz, ldp, nsplit);
    k2b_pr<<<dim3(2, 2), dim3(16, 16)>>>(W);
    k3_out<<<dim3(nsplit, 2), 128>>>(Qreal, Qimag, real, imag, out, N);
}

// round 9
// speedup vs baseline: 3.3158x; 1.1149x over previous
#include <cuda_runtime.h>
#include <cuda_bf16.h>
#include <cstdint>

#define CDIM 128
#define NS1 74
#define PQ 72   // bf16 tile pitch (144B) for 64-wide tiles: conflict-free LDSM
#define PQA 40  // bf16 tile pitch (80B) for 32-wide tiles: conflict-free LDSM

__device__ float g_part[2][80][64][CDIM];   // 5.2 MB
__device__ float g_UV[2][64][CDIM];
__device__ unsigned short g_Ph[64][128], g_Pl[64][128];
__device__ unsigned short g_Rh[64][128], g_Rl[64][128];

// ---------------------------------------------------------------------------
// helpers
// ---------------------------------------------------------------------------
__device__ __forceinline__ unsigned sadr(const void* p) {
    return (unsigned)__cvta_generic_to_shared(p);
}
__device__ __forceinline__ uint32_t pk2(float x0, float x1) {
    uint32_t d;
    asm("cvt.rn.bf16x2.f32 %0, %2, %1;" : "=r"(d) : "f"(x0), "f"(x1));
    return d;
}
__device__ __forceinline__ float bfr(float x) {
    return __bfloat162float(__float2bfloat16(x));
}
__device__ __forceinline__ void cvst(unsigned short* hp, unsigned short* lp, float4 a) {
    ((uint32_t*)hp)[0] = pk2(a.x, a.y);
    ((uint32_t*)hp)[1] = pk2(a.z, a.w);
    float l0 = a.x - bfr(a.x), l1 = a.y - bfr(a.y);
    float l2 = a.z - bfr(a.z), l3 = a.w - bfr(a.w);
    ((uint32_t*)lp)[0] = pk2(l0, l1);
    ((uint32_t*)lp)[1] = pk2(l2, l3);
}
__device__ __forceinline__ void ldmA(uint32_t* a, unsigned addr) {
    asm volatile("ldmatrix.sync.aligned.m8n8.x4.shared.b16 {%0,%1,%2,%3},[%4];"
        : "=r"(a[0]), "=r"(a[1]), "=r"(a[2]), "=r"(a[3]) : "r"(addr));
}
__device__ __forceinline__ void ldmAT(uint32_t* a, unsigned addr) {
    asm volatile("ldmatrix.sync.aligned.m8n8.x4.trans.shared.b16 {%0,%1,%2,%3},[%4];"
        : "=r"(a[0]), "=r"(a[1]), "=r"(a[2]), "=r"(a[3]) : "r"(addr));
}
__device__ __forceinline__ void ldmBT(uint32_t* b, unsigned addr) {
    asm volatile("ldmatrix.sync.aligned.m8n8.x2.trans.shared.b16 {%0,%1},[%2];"
        : "=r"(b[0]), "=r"(b[1]) : "r"(addr));
}
__device__ __forceinline__ void mma(float* d, const uint32_t* a, const uint32_t* b) {
    asm volatile("mma.sync.aligned.m16n8k16.row.col.f32.bf16.bf16.f32 "
        "{%0,%1,%2,%3},{%4,%5,%6,%7},{%8,%9},{%0,%1,%2,%3};"
        : "+f"(d[0]), "+f"(d[1]), "+f"(d[2]), "+f"(d[3])
        : "r"(a[0]), "r"(a[1]), "r"(a[2]), "r"(a[3]), "r"(b[0]), "r"(b[1]));
}
#define NEG4(dst, src) { dst[0]=src[0]^0x80008000u; dst[1]=src[1]^0x80008000u; \
                         dst[2]=src[2]^0x80008000u; dst[3]=src[3]^0x80008000u; }

// ---------------------------------------------------------------------------
// Kernel 1: U/V partials, chunk loop with register prefetch.
// grid (NS1, 2 c-halves), block 256: 8 warps = 4 k-slabs(16) x 2 c-sub(32).
// Chunk ci = s + t*NS1 (strided, balanced). Accumulate in regs across chunks.
// ---------------------------------------------------------------------------
__global__ __launch_bounds__(256, 1) void k1_partial(
    const float* __restrict__ Qr, const float* __restrict__ Qi,
    const float* __restrict__ re, const float* __restrict__ im, int N)
{
    __shared__ unsigned short sQrh[32][PQ], sQrl[32][PQ], sQih[32][PQ], sQil[32][PQ];
    __shared__ unsigned short sXrh[32][PQ], sXrl[32][PQ], sXih[32][PQ], sXil[32][PQ];

    const int s  = blockIdx.x;
    const int c0 = blockIdx.y * 64;
    const int tid = threadIdx.x;
    const int nchunks = (N + 31) >> 5;
    const float4 f4z = make_float4(0.f, 0.f, 0.f, 0.f);

    const int lane = tid & 31, warp = tid >> 5;
    const int m0 = (warp & 3) * 16;        // k-slab
    const int cs = (warp >> 2) * 32;       // c-sub
    const int r8 = lane & 7, sel = lane >> 3;
    const int atrow = ((sel >> 1) & 1) * 8 + r8;
    const int atcol = m0 + (sel & 1) * 8;
    const int brow = lane & 15;
    const int gid = lane >> 2, tig = lane & 3;

    float u[4][4] = {};
    float v[4][4] = {};

    float4 qa[2], qb[2], xa[2], xb[2];
    auto ldchunk = [&](int ci) {
        #pragma unroll
        for (int q = 0; q < 2; q++) {
            int f = tid + 256 * q;
            int row = f >> 4, k4 = (f & 15) * 4;
            int n = ci * 32 + row;
            bool ok = (n < N);
            qa[q] = ok ? *(const float4*)(Qr + (long)n * 64 + k4) : f4z;
            qb[q] = ok ? *(const float4*)(Qi + (long)n * 64 + k4) : f4z;
            xa[q] = ok ? *(const float4*)(re + (long)n * 128 + c0 + k4) : f4z;
            xb[q] = ok ? *(const float4*)(im + (long)n * 128 + c0 + k4) : f4z;
        }
    };

    ldchunk(s);
    for (int t = 0;; t++) {
        int ci = s + t * NS1;
        if (ci >= nchunks) break;                     // CTA-uniform
        #pragma unroll
        for (int q = 0; q < 2; q++) {
            int f = tid + 256 * q;
            int row = f >> 4, k4 = (f & 15) * 4;
            cvst(&sQrh[row][k4], &sQrl[row][k4], qa[q]);
            cvst(&sQih[row][k4], &sQil[row][k4], qb[q]);
            cvst(&sXrh[row][k4], &sXrl[row][k4], xa[q]);
            cvst(&sXih[row][k4], &sXil[row][k4], xb[q]);
        }
        __syncthreads();
        int cin = ci + NS1;
        if (cin < nchunks) ldchunk(cin);              // prefetch under MMA

        #pragma unroll
        for (int ks = 0; ks < 2; ks++) {
            const int n0k = ks * 16;
            uint32_t qrh[4], qrl[4], qih[4], qil[4], nqh[4], nql[4];
            ldmAT(qrh, sadr(&sQrh[n0k + atrow][atcol]));
            ldmAT(qrl, sadr(&sQrl[n0k + atrow][atcol]));
            ldmAT(qih, sadr(&sQih[n0k + atrow][atcol]));
            ldmAT(qil, sadr(&sQil[n0k + atrow][atcol]));
            NEG4(nqh, qrh);
            NEG4(nql, qrl);
            #pragma unroll
            for (int nt = 0; nt < 4; nt++) {
                uint32_t xh[2], xl[2], yh[2], yl[2];
                ldmBT(xh, sadr(&sXrh[n0k + brow][cs + nt * 8]));
                ldmBT(xl, sadr(&sXrl[n0k + brow][cs + nt * 8]));
                ldmBT(yh, sadr(&sXih[n0k + brow][cs + nt * 8]));
                ldmBT(yl, sadr(&sXil[n0k + brow][cs + nt * 8]));
                mma(u[nt], qrh, xh); mma(u[nt], qrh, xl); mma(u[nt], qrl, xh);
                mma(u[nt], qih, yh); mma(u[nt], qih, yl); mma(u[nt], qil, yh);
                mma(v[nt], qih, xh); mma(v[nt], qih, xl); mma(v[nt], qil, xh);
                mma(v[nt], nqh, yh); mma(v[nt], nqh, yl); mma(v[nt], nql, yh);
            }
        }
        __syncthreads();
    }

    #pragma unroll
    for (int nt = 0; nt < 4; nt++) {
        int k = m0 + gid;
        int c = c0 + cs + nt * 8 + tig * 2;
        *(float2*)&g_part[0][s][k][c]     = make_float2(u[nt][0], u[nt][1]);
        *(float2*)&g_part[0][s][k + 8][c] = make_float2(u[nt][2], u[nt][3]);
        *(float2*)&g_part[1][s][k][c]     = make_float2(v[nt][0], v[nt][1]);
        *(float2*)&g_part[1][s][k + 8][c] = make_float2(v[nt][2], v[nt][3]);
    }
}

// ---------------------------------------------------------------------------
// Kernel 2a: reduce partials over splits, scale row k by TT = Ritz[k]^ld.
// ---------------------------------------------------------------------------
__global__ __launch_bounds__(256) void k2a_reduce(
    const float* __restrict__ Ritz, const int* __restrict__ ldp, int nsplit)
{
    __shared__ float red[256];
    const int o   = threadIdx.x & 31;
    const int seg = threadIdx.x >> 5;
    const int t   = blockIdx.x * 32 + o;       // 0..16383
    const int uv  = t >> 13;
    const int rem = t & 8191;

    const float* p = &g_part[uv][0][0][0] + rem;
    float sum = 0.f;
    for (int s2 = seg; s2 < nsplit; s2 += 8) sum += p[(long)s2 * 8192];
    red[threadIdx.x] = sum;
    __syncthreads();

    if (threadIdx.x < 32) {
        #pragma unroll
        for (int g = 1; g < 8; g++) sum += red[g * 32 + o];
        int k = rem >> 7;
        int ld = *ldp;
        float rz = Ritz[k];
        float tt = 1.f;
        for (int i = 0; i < ld; i++) tt *= rz;
        (&g_UV[0][0][0])[t] = tt * sum;
    }
}

// ---------------------------------------------------------------------------
// Kernel 2b: P = U' @ W, R = V' @ W  ([64,128]@[128,128]); bf16 hi/lo outputs.
// ---------------------------------------------------------------------------
__global__ __launch_bounds__(256) void k2b_pr(const float* __restrict__ W)
{
    __shared__ float sA[64 * 68];
    __shared__ float sW[64 * 64];

    const int m   = blockIdx.x;
    const int cp0 = blockIdx.y * 64;
    const int tx = threadIdx.x, ty = threadIdx.y;
    const int tid = ty * 16 + tx;

    float acc[4][4] = {};

    for (int cc = 0; cc < 128; cc += 64) {
        #pragma unroll
        for (int q = 0; q < 4; q++) {
            int f   = tid + 256 * q;
            int row = f >> 4;
            int c4  = (f & 15) * 4;
            *(float4*)&sA[row * 68 + c4] = *(const float4*)&g_UV[m][row][cc + c4];
            *(float4*)&sW[row * 64 + c4] = *(const float4*)(W + (cc + row) * 128 + cp0 + c4);
        }
        __syncthreads();

        #pragma unroll 4
        for (int r = 0; r < 64; r++) {
            float a[4];
            #pragma unroll
            for (int i = 0; i < 4; i++) a[i] = sA[(ty * 4 + i) * 68 + r];
            float4 w4 = *(float4*)&sW[r * 64 + tx * 4];
            float wj[4] = {w4.x, w4.y, w4.z, w4.w};
            #pragma unroll
            for (int i = 0; i < 4; i++)
                #pragma unroll
                for (int j = 0; j < 4; j++)
                    acc[i][j] += a[i] * wj[j];
        }
        __syncthreads();
    }

    unsigned short (*Dh)[128] = (m == 0) ? g_Ph : g_Rh;
    unsigned short (*Dl)[128] = (m == 0) ? g_Pl : g_Rl;
    #pragma unroll
    for (int i = 0; i < 4; i++) {
        int k = ty * 4 + i;
        int c = cp0 + tx * 4;
        ((uint32_t*)&Dh[k][c])[0] = pk2(acc[i][0], acc[i][1]);
        ((uint32_t*)&Dh[k][c])[1] = pk2(acc[i][2], acc[i][3]);
        float l0 = acc[i][0] - bfr(acc[i][0]), l1 = acc[i][1] - bfr(acc[i][1]);
        float l2 = acc[i][2] - bfr(acc[i][2]), l3 = acc[i][3] - bfr(acc[i][3]);
        ((uint32_t*)&Dl[k][c])[0] = pk2(l0, l1);
        ((uint32_t*)&Dl[k][c])[1] = pk2(l2, l3);
    }
}

// ---------------------------------------------------------------------------
// Kernel 3: res_real = Qr@P + Qi@R, res_imag = Qi@P - Qr@R (MMA 3-pass),
// masked-ReLU epilogue. grid (ceil(N/64), 2 c-halves), block 128:
// 4 warps = 4 n-slabs of 16; each warp covers the full 64-c half (8 n-tiles).
// Two k-phases of 32 (Q + P/R halves staged per phase, 38.9 KB static smem).
// ---------------------------------------------------------------------------
__global__ __launch_bounds__(128, 2) void k3_out(
    const float* __restrict__ Qr, const float* __restrict__ Qi,
    const float* __restrict__ re, const float* __restrict__ im,
    float* __restrict__ out, int N)
{
    __shared__ unsigned short sQrh[64][PQA], sQrl[64][PQA], sQih[64][PQA], sQil[64][PQA];
    __shared__ unsigned short sPh[32][PQ], sPl[32][PQ], sRh[32][PQ], sRl[32][PQ];

    const int n0 = blockIdx.x * 64;
    const int c0 = blockIdx.y * 64;
    const int tid = threadIdx.x;
    const float4 f4z = make_float4(0.f, 0.f, 0.f, 0.f);

    const int lane = tid & 31, warp = tid >> 5;
    const int m0 = warp * 16;                 // n-slab
    const int arow = m0 + (lane & 15);
    const int acol8 = (lane >> 4) * 8;
    const int brow = lane & 15;
    const int gid = lane >> 2, tig = lane & 3;

    float sr[8][4] = {};
    float si[8][4] = {};

    #pragma unroll
    for (int ph = 0; ph < 2; ph++) {
        const int kk = ph * 32;
        // batched reg-first loads: Q k-half (fp32->convert) + P/R k-half (bf16 copy)
        float4 qa[4], qb[4];
        uint4 pv[2], plv[2], rv[2], rlv[2];
        #pragma unroll
        for (int q = 0; q < 4; q++) {
            int f = tid + 128 * q;
            int row = f >> 3, k4 = (f & 7) * 4;
            int n = n0 + row;
            bool ok = (n < N);
            qa[q] = ok ? *(const float4*)(Qr + (long)n * 64 + kk + k4) : f4z;
            qb[q] = ok ? *(const float4*)(Qi + (long)n * 64 + kk + k4) : f4z;
        }
        #pragma unroll
        for (int q = 0; q < 2; q++) {
            int f = tid + 128 * q;
            int row = f >> 3, cu = (f & 7);
            pv[q]  = *(const uint4*)&g_Ph[kk + row][c0 + cu * 8];
            plv[q] = *(const uint4*)&g_Pl[kk + row][c0 + cu * 8];
            rv[q]  = *(const uint4*)&g_Rh[kk + row][c0 + cu * 8];
            rlv[q] = *(const uint4*)&g_Rl[kk + row][c0 + cu * 8];
        }
        if (ph) __syncthreads();   // protect previous phase reads before overwrite
        #pragma unroll
        for (int q = 0; q < 4; q++) {
            int f = tid + 128 * q;
            int row = f >> 3, k4 = (f & 7) * 4;
            cvst(&sQrh[row][k4], &sQrl[row][k4], qa[q]);
            cvst(&sQih[row][k4], &sQil[row][k4], qb[q]);
        }
        #pragma unroll
        for (int q = 0; q < 2; q++) {
            int f = tid + 128 * q;
            int row = f >> 3, cu = (f & 7);
            *(uint4*)&sPh[row][cu * 8] = pv[q];
            *(uint4*)&sPl[row][cu * 8] = plv[q];
            *(uint4*)&sRh[row][cu * 8] = rv[q];
            *(uint4*)&sRl[row][cu * 8] = rlv[q];
        }
        __syncthreads();

        #pragma unroll
        for (int ks = 0; ks < 2; ks++) {
            const int k0 = ks * 16;
            uint32_t qrh[4], qrl[4], qih[4], qil[4], nqh[4], nql[4];
            ldmA(qrh, sadr(&sQrh[arow][k0 + acol8]));
            ldmA(qrl, sadr(&sQrl[arow][k0 + acol8]));
            ldmA(qih, sadr(&sQih[arow][k0 + acol8]));
            ldmA(qil, sadr(&sQil[arow][k0 + acol8]));
            NEG4(nqh, qrh);
            NEG4(nql, qrl);
            #pragma unroll
            for (int nt = 0; nt < 8; nt++) {
                uint32_t pf[2], pl[2], rf[2], rl2[2];
                ldmBT(pf,  sadr(&sPh[k0 + brow][nt * 8]));
                ldmBT(pl,  sadr(&sPl[k0 + brow][nt * 8]));
                ldmBT(rf,  sadr(&sRh[k0 + brow][nt * 8]));
                ldmBT(rl2, sadr(&sRl[k0 + brow][nt * 8]));
                mma(sr[nt], qrh, pf);  mma(sr[nt], qrh, pl);  mma(sr[nt], qrl, pf);
                mma(sr[nt], qih, rf);  mma(sr[nt], qih, rl2); mma(sr[nt], qil, rf);
                mma(si[nt], qih, pf);  mma(si[nt], qih, pl);  mma(si[nt], qil, pf);
                mma(si[nt], nqh, rf);  mma(si[nt], nqh, rl2); mma(si[nt], nql, rf);
            }
        }
    }

    // epilogue: masked-ReLU add, write out
    const long NC = (long)N * 128;
    #pragma unroll
    for (int nt = 0; nt < 8; nt++) {
        int c = c0 + nt * 8 + tig * 2;
        int r0 = n0 + m0 + gid;
        int r1 = r0 + 8;
        if (r0 < N) {
            long base = (long)r0 * 128 + c;
            float2 rvv = *(const float2*)(re + base);
            float2 ivv = *(const float2*)(im + base);
            float mk0 = (sr[nt][0] >= 0.f) ? 1.f : 0.f;
            float mk1 = (sr[nt][1] >= 0.f) ? 1.f : 0.f;
            *(float2*)(out + base)      = make_float2(rvv.x + mk0 * sr[nt][0], rvv.y + mk1 * sr[nt][1]);
            *(float2*)(out + NC + base) = make_float2(ivv.x + mk0 * si[nt][0], ivv.y + mk1 * si[nt][1]);
        }
        if (r1 < N) {
            long base = (long)r1 * 128 + c;
            float2 rvv = *(const float2*)(re + base);
            float2 ivv = *(const float2*)(im + base);
            float mk2 = (sr[nt][2] >= 0.f) ? 1.f : 0.f;
            float mk3 = (sr[nt][3] >= 0.f) ? 1.f : 0.f;
            *(float2*)(out + base)      = make_float2(rvv.x + mk2 * sr[nt][2], rvv.y + mk3 * sr[nt][3]);
            *(float2*)(out + NC + base) = make_float2(ivv.x + mk2 * si[nt][2], ivv.y + mk3 * si[nt][3]);
        }
    }
}

// ---------------------------------------------------------------------------
extern "C" void kernel_launch(void* const* d_in, const int* in_sizes, int n_in,
                              void* d_out, int out_size)
{
    const float* real  = (const float*)d_in[0];
    const float* imag  = (const float*)d_in[1];
    const float* Qreal = (const float*)d_in[2];
    const float* Qimag = (const float*)d_in[3];
    const float* Ritz  = (const float*)d_in[4];
    const float* W     = (const float*)d_in[5];
    const int*   ldp   = (const int*)d_in[6];
    float* out = (float*)d_out;

    int N = in_sizes[0] / CDIM;
    int nchunks = (N + 31) / 32;
    int nsplit = (nchunks < NS1) ? nchunks : NS1;

    k1_partial<<<dim3(NS1, 2), 256>>>(Qreal, Qimag, real, imag, N);
    k2a_reduce<<<512, 256>>>(Ritz, ldp, nsplit);
    k2b_pr<<<dim3(2, 2), dim3(16, 16)>>>(W);
    k3_out<<<dim3((N + 63) / 64, 2), 128>>>(Qreal, Qimag, real, imag, out, N);
}